// round 2
// baseline (speedup 1.0000x reference)
#include <cuda_runtime.h>
#include <cuda_bf16.h>
#include <math.h>

// ---------------- scratch (no allocation allowed) ----------------
__device__ float g_lines[3 * 2 * 64 * 32];   // [axis][bs/jaw][l][c]
__device__ float g_P[3 * 64 * 128];          // [axis][l][j] layer0-folded tables
__device__ float g_W1[128 * 128];            // weight-normed W1
__device__ float g_w2[128];                  // weight-normed w2 row

// ---------------- kernel A: weighted line sums ----------------
// grid (64, 3), 32 threads; block.x = l, block.y = axis, thread = c
__global__ void lines_kernel(const float* __restrict__ expr,
                             const float* __restrict__ jw,
                             const float* __restrict__ flx,
                             const float* __restrict__ fly,
                             const float* __restrict__ flz) {
    int l = blockIdx.x, a = blockIdx.y, c = threadIdx.x;
    const float* fl = (a == 0) ? flx : ((a == 1) ? fly : flz);
    const float* base = fl + l * 32 + c;
    float bs = 0.f, jaw = 0.f;
#pragma unroll 4
    for (int i = 0; i < 80; i++) bs += base[i * 2048] * expr[i];
#pragma unroll
    for (int i = 0; i < 16; i++) jaw += base[(80 + i) * 2048] * jw[i];
    g_lines[((a * 2 + 0) * 64 + l) * 32 + c] = bs;
    g_lines[((a * 2 + 1) * 64 + l) * 32 + c] = jaw;
}

// ---------------- kernel B: weight-norm W1 and w2 ----------------
// grid 129 blocks x 128 threads. blocks 0..127 -> W1 rows, block 128 -> w2.
__global__ void wnorm_kernel(const float* __restrict__ w1_v,
                             const float* __restrict__ w1_g,
                             const float* __restrict__ w2_v,
                             const float* __restrict__ w2_g) {
    __shared__ float red[128];
    int j = blockIdx.x, t = threadIdx.x;
    const float* row = (j < 128) ? (w1_v + j * 128) : w2_v;
    float v = row[t];
    red[t] = v * v;
    __syncthreads();
    for (int s = 64; s > 0; s >>= 1) {
        if (t < s) red[t] += red[t + s];
        __syncthreads();
    }
    float g = (j < 128) ? w1_g[j] : w2_g[0];
    float scale = g / sqrtf(red[0]);
    if (j < 128) g_W1[j * 128 + t] = v * scale;
    else         g_w2[t] = v * scale;
}

// ---------------- kernel C: fold W0 into per-axis tables ----------------
// grid (64, 3) x 128 threads; thread = output channel j
__global__ void table_kernel(const float* __restrict__ w0_v,
                             const float* __restrict__ w0_g) {
    int l = blockIdx.x, a = blockIdx.y, j = threadIdx.x;
    const float* vrow = w0_v + j * 192;
    float nn = 0.f;
#pragma unroll 8
    for (int c = 0; c < 192; c++) { float v = vrow[c]; nn += v * v; }
    float s = w0_g[j] / sqrtf(nn);
    const float* bs  = &g_lines[((a * 2 + 0) * 64 + l) * 32];
    const float* jl  = &g_lines[((a * 2 + 1) * 64 + l) * 32];
    float acc = 0.f;
#pragma unroll
    for (int c = 0; c < 32; c++) acc += vrow[32 * a + c] * bs[c];
#pragma unroll
    for (int c = 0; c < 32; c++) acc += vrow[96 + 32 * a + c] * jl[c];
    g_P[(a * 64 + l) * 128 + j] = s * acc;
}

// ---------------- kernel D: main per-point MLP ----------------
constexpr int TPB = 256;
constexpr int PPT = 8;                 // points per thread
constexpr int TSTRIDE = 132;           // padded table row stride (floats), 16B aligned
// smem layout (floats): tables 3*64*132 = 25344 | W1 16384 | b0 128 | b1 128 | w2 128
constexpr int SM_T  = 0;
constexpr int SM_W1 = 25344;
constexpr int SM_B0 = SM_W1 + 16384;
constexpr int SM_B1 = SM_B0 + 128;
constexpr int SM_W2 = SM_B1 + 128;
constexpr int SM_FLOATS = SM_W2 + 128;      // 42112 floats = 168448 bytes

__global__ __launch_bounds__(TPB, 1)
void mlp_kernel(const float* __restrict__ xyz,
                const float* __restrict__ b0,
                const float* __restrict__ b1,
                const float* __restrict__ b2p,
                float* __restrict__ out, int n) {
    extern __shared__ float sm[];
    float* sT  = sm + SM_T;
    float* sW1 = sm + SM_W1;
    float* sb0 = sm + SM_B0;
    float* sb1 = sm + SM_B1;
    float* sw2 = sm + SM_W2;

    // fill shared: tables with stride re-pack 128 -> 132
    for (int i = threadIdx.x; i < 3 * 64 * 128; i += TPB) {
        int al = i >> 7, j = i & 127;
        sT[al * TSTRIDE + j] = g_P[i];
    }
    {
        float4* dst = (float4*)sW1;
        const float4* src = (const float4*)g_W1;
        for (int i = threadIdx.x; i < 128 * 128 / 4; i += TPB) dst[i] = src[i];
    }
    for (int i = threadIdx.x; i < 128; i += TPB) {
        sb0[i] = b0[i]; sb1[i] = b1[i]; sw2[i] = g_w2[i];
    }
    __syncthreads();

    float bias2 = b2p[0];
    int base = blockIdx.x * (TPB * PPT) + threadIdx.x;

    for (int it = 0; it < PPT; ++it) {
        int idx = base + it * TPB;
        if (idx >= n) return;

        float cx = xyz[idx * 3 + 0];
        float cy = xyz[idx * 3 + 1];
        float cz = xyz[idx * 3 + 2];

        const float4* rowp[6];
        float wts[3];
        float coords[3] = {cx, cy, cz};
#pragma unroll
        for (int a = 0; a < 3; a++) {
            float p = fminf(fmaxf(coords[a], 0.f), 1.f) * 63.f;
            float fl = floorf(p);
            int l = (int)fl;
            int r = min(l + 1, 63);
            wts[a] = p - fl;
            rowp[2 * a]     = (const float4*)&sT[(a * 64 + l) * TSTRIDE];
            rowp[2 * a + 1] = (const float4*)&sT[(a * 64 + r) * TSTRIDE];
        }

        // h0 = relu(lerp_x + lerp_y + lerp_z + b0)
        float h0[128];
        const float4* bb0 = (const float4*)sb0;
#pragma unroll
        for (int kk = 0; kk < 32; kk++) {
            float4 x0 = rowp[0][kk], x1 = rowp[1][kk];
            float4 y0 = rowp[2][kk], y1 = rowp[3][kk];
            float4 z0 = rowp[4][kk], z1 = rowp[5][kk];
            float4 bv = bb0[kk];
            float v0 = bv.x + x0.x + wts[0] * (x1.x - x0.x)
                            + y0.x + wts[1] * (y1.x - y0.x)
                            + z0.x + wts[2] * (z1.x - z0.x);
            float v1 = bv.y + x0.y + wts[0] * (x1.y - x0.y)
                            + y0.y + wts[1] * (y1.y - y0.y)
                            + z0.y + wts[2] * (z1.y - z0.y);
            float v2 = bv.z + x0.z + wts[0] * (x1.z - x0.z)
                            + y0.z + wts[1] * (y1.z - y0.z)
                            + z0.z + wts[2] * (z1.z - z0.z);
            float v3 = bv.w + x0.w + wts[0] * (x1.w - x0.w)
                            + y0.w + wts[1] * (y1.w - y0.w)
                            + z0.w + wts[2] * (z1.w - z0.w);
            h0[4 * kk + 0] = fmaxf(v0, 0.f);
            h0[4 * kk + 1] = fmaxf(v1, 0.f);
            h0[4 * kk + 2] = fmaxf(v2, 0.f);
            h0[4 * kk + 3] = fmaxf(v3, 0.f);
        }

        // layer1 (128x128) + layer2 fused
        float acc = bias2;
        for (int j = 0; j < 128; j++) {
            const float4* wr = (const float4*)&sW1[j * 128];
            float s0 = 0.f, s1 = 0.f, s2 = 0.f, s3 = 0.f;
#pragma unroll
            for (int kk = 0; kk < 32; kk++) {
                float4 wv = wr[kk];          // broadcast LDS.128 (all lanes same addr)
                s0 += wv.x * h0[4 * kk + 0];
                s1 += wv.y * h0[4 * kk + 1];
                s2 += wv.z * h0[4 * kk + 2];
                s3 += wv.w * h0[4 * kk + 3];
            }
            float s = ((s0 + s1) + (s2 + s3)) + sb1[j];
            acc += sw2[j] * fmaxf(s, 0.f);
        }
        out[idx] = acc;
    }
}

// ---------------- launch ----------------
extern "C" void kernel_launch(void* const* d_in, const int* in_sizes, int n_in,
                              void* d_out, int out_size) {
    const float* expr = (const float*)d_in[0];
    const float* jqw  = (const float*)d_in[1];
    const float* xyz  = (const float*)d_in[2];
    const float* flx  = (const float*)d_in[3];
    const float* fly  = (const float*)d_in[4];
    const float* flz  = (const float*)d_in[5];
    const float* w0_v = (const float*)d_in[6];
    const float* w0_g = (const float*)d_in[7];
    const float* b0   = (const float*)d_in[8];
    const float* w1_v = (const float*)d_in[9];
    const float* w1_g = (const float*)d_in[10];
    const float* b1   = (const float*)d_in[11];
    const float* w2_v = (const float*)d_in[12];
    const float* w2_g = (const float*)d_in[13];
    const float* b2   = (const float*)d_in[14];
    float* out = (float*)d_out;

    int n = in_sizes[2] / 3;

    lines_kernel<<<dim3(64, 3), 32>>>(expr, jqw, flx, fly, flz);
    wnorm_kernel<<<129, 128>>>(w1_v, w1_g, w2_v, w2_g);
    table_kernel<<<dim3(64, 3), 128>>>(w0_v, w0_g);

    cudaFuncSetAttribute(mlp_kernel,
                         cudaFuncAttributeMaxDynamicSharedMemorySize,
                         SM_FLOATS * sizeof(float));
    int nblocks = (n + TPB * PPT - 1) / (TPB * PPT);
    mlp_kernel<<<nblocks, TPB, SM_FLOATS * sizeof(float)>>>(xyz, b0, b1, b2, out, n);
}

// round 9
// speedup vs baseline: 1.5942x; 1.5942x over previous
#include <cuda_runtime.h>
#include <cuda_bf16.h>
#include <math.h>

// ---------------- scratch (no allocation allowed) ----------------
__device__ float g_lines[3 * 2 * 64 * 32];   // [axis][bs/jaw][l][c]
__device__ float g_P[3 * 64 * 128];          // [axis][l][j] layer0-folded tables (+b0/3)
__device__ float g_W1T[128 * 128];           // weight-normed W1, TRANSPOSED [k][j]
__device__ float g_w2[128];                  // weight-normed w2 row

// ---------------- f32x2 packed helpers ----------------
__device__ __forceinline__ unsigned long long fma2(unsigned long long a,
                                                   unsigned long long b,
                                                   unsigned long long c) {
    unsigned long long d;
    asm("fma.rn.f32x2 %0, %1, %2, %3;" : "=l"(d) : "l"(a), "l"(b), "l"(c));
    return d;
}
__device__ __forceinline__ unsigned long long dup2(float s) {
    unsigned long long d;
    asm("mov.b64 %0, {%1, %1};" : "=l"(d) : "f"(s));
    return d;
}
__device__ __forceinline__ void unpack2(unsigned long long v, float& lo, float& hi) {
    asm("mov.b64 {%0, %1}, %2;" : "=f"(lo), "=f"(hi) : "l"(v));
}

// ---------------- kernel A: weighted line sums ----------------
__global__ void lines_kernel(const float* __restrict__ expr,
                             const float* __restrict__ jw,
                             const float* __restrict__ flx,
                             const float* __restrict__ fly,
                             const float* __restrict__ flz) {
    int l = blockIdx.x, a = blockIdx.y, c = threadIdx.x;
    const float* fl = (a == 0) ? flx : ((a == 1) ? fly : flz);
    const float* base = fl + l * 32 + c;
    float bs = 0.f, jaw = 0.f;
#pragma unroll 4
    for (int i = 0; i < 80; i++) bs += base[i * 2048] * expr[i];
#pragma unroll
    for (int i = 0; i < 16; i++) jaw += base[(80 + i) * 2048] * jw[i];
    g_lines[((a * 2 + 0) * 64 + l) * 32 + c] = bs;
    g_lines[((a * 2 + 1) * 64 + l) * 32 + c] = jaw;
}

// ---------------- kernel B: weight-norm W1 (transposed) and w2 ----------------
__global__ void wnorm_kernel(const float* __restrict__ w1_v,
                             const float* __restrict__ w1_g,
                             const float* __restrict__ w2_v,
                             const float* __restrict__ w2_g) {
    __shared__ float red[128];
    int j = blockIdx.x, t = threadIdx.x;
    const float* row = (j < 128) ? (w1_v + j * 128) : w2_v;
    float v = row[t];
    red[t] = v * v;
    __syncthreads();
    for (int s = 64; s > 0; s >>= 1) {
        if (t < s) red[t] += red[t + s];
        __syncthreads();
    }
    float g = (j < 128) ? w1_g[j] : w2_g[0];
    float scale = g / sqrtf(red[0]);
    if (j < 128) g_W1T[t * 128 + j] = v * scale;   // transposed: [k=t][j]
    else         g_w2[t] = v * scale;
}

// ---------------- kernel C: fold W0 (+ b0/3) into per-axis tables ----------------
__global__ void table_kernel(const float* __restrict__ w0_v,
                             const float* __restrict__ w0_g,
                             const float* __restrict__ b0) {
    int l = blockIdx.x, a = blockIdx.y, j = threadIdx.x;
    const float* vrow = w0_v + j * 192;
    float nn = 0.f;
#pragma unroll 8
    for (int c = 0; c < 192; c++) { float v = vrow[c]; nn += v * v; }
    float s = w0_g[j] / sqrtf(nn);
    const float* bs  = &g_lines[((a * 2 + 0) * 64 + l) * 32];
    const float* jl  = &g_lines[((a * 2 + 1) * 64 + l) * 32];
    float acc = 0.f;
#pragma unroll
    for (int c = 0; c < 32; c++) acc += vrow[32 * a + c] * bs[c];
#pragma unroll
    for (int c = 0; c < 32; c++) acc += vrow[96 + 32 * a + c] * jl[c];
    // fold b0/3 into each axis (lerp weights sum to 1 -> constants pass through)
    g_P[(a * 64 + l) * 128 + j] = s * acc + b0[j] * (1.0f / 3.0f);
}

// ---------------- kernel D: main per-point MLP ----------------
constexpr int TPB = 256;
constexpr int CHUNK = 64;              // points per chunk
constexpr int TSTRIDE = 132;           // padded table row stride (floats)
constexpr int HSTRIDE = 68;            // h0T row stride (floats), pad 64->68

// smem (floats): tables 3*64*132 = 25344 | W1T 16384 | h0T 128*68 = 8704 | b1 128 | w2 128
constexpr int SM_T   = 0;
constexpr int SM_W1T = 25344;
constexpr int SM_H   = SM_W1T + 16384;      // 41728
constexpr int SM_B1  = SM_H + 128 * HSTRIDE; // 50432
constexpr int SM_W2  = SM_B1 + 128;
constexpr int SM_FLOATS = SM_W2 + 128;       // 50688 floats = 202752 bytes

__global__ __launch_bounds__(TPB, 1)
void mlp_kernel(const float* __restrict__ xyz,
                const float* __restrict__ b1,
                const float* __restrict__ b2p,
                float* __restrict__ out, int n) {
    extern __shared__ float sm[];
    float* sT   = sm + SM_T;
    float* sW1T = sm + SM_W1T;
    float* sH   = sm + SM_H;
    float* sb1  = sm + SM_B1;
    float* sw2  = sm + SM_W2;

    // ---- one-time shared fill ----
    for (int i = threadIdx.x; i < 3 * 64 * 128; i += TPB) {
        int al = i >> 7, j = i & 127;
        sT[al * TSTRIDE + j] = g_P[i];
    }
    {
        float4* dst = (float4*)sW1T;
        const float4* src = (const float4*)g_W1T;
        for (int i = threadIdx.x; i < 128 * 128 / 4; i += TPB) dst[i] = src[i];
    }
    for (int i = threadIdx.x; i < 128; i += TPB) {
        sb1[i] = b1[i]; sw2[i] = g_w2[i];
    }
    __syncthreads();

    const float bias2 = b2p[0];
    const int tid  = threadIdx.x;
    const int lane = tid & 31;
    const int wid  = tid >> 5;
    const int p_local = tid & 63;          // phase-1 point within chunk
    const int sub     = tid >> 6;          // phase-1 channel quarter (0..3)
    const int nchunks = (n + CHUNK - 1) / CHUNK;

    for (int c = blockIdx.x; c < nchunks; c += gridDim.x) {
        const int base = c * CHUNK;

        // ================= phase 1: h0 for 64 points -> sH[k][p] =================
        {
            const int idx = base + p_local;
            if (idx < n) {
                float coords[3];
                coords[0] = xyz[idx * 3 + 0];
                coords[1] = xyz[idx * 3 + 1];
                coords[2] = xyz[idx * 3 + 2];
                const float4* rowL[3];
                const float4* rowR[3];
                float wts[3];
#pragma unroll
                for (int a = 0; a < 3; a++) {
                    float p = fminf(fmaxf(coords[a], 0.f), 1.f) * 63.f;
                    float fl = floorf(p);
                    int l = (int)fl;
                    int r = min(l + 1, 63);
                    wts[a] = p - fl;
                    rowL[a] = (const float4*)&sT[(a * 64 + l) * TSTRIDE];
                    rowR[a] = (const float4*)&sT[(a * 64 + r) * TSTRIDE];
                }
                const int chbase = sub * 32;
#pragma unroll
                for (int c4 = 0; c4 < 8; c4++) {
                    const int ch = chbase + c4 * 4;
                    const int q = ch >> 2;
                    float4 x0 = rowL[0][q], x1 = rowR[0][q];
                    float4 y0 = rowL[1][q], y1 = rowR[1][q];
                    float4 z0 = rowL[2][q], z1 = rowR[2][q];
                    float v0 = x0.x + wts[0] * (x1.x - x0.x)
                             + y0.x + wts[1] * (y1.x - y0.x)
                             + z0.x + wts[2] * (z1.x - z0.x);
                    float v1 = x0.y + wts[0] * (x1.y - x0.y)
                             + y0.y + wts[1] * (y1.y - y0.y)
                             + z0.y + wts[2] * (z1.y - z0.y);
                    float v2 = x0.z + wts[0] * (x1.z - x0.z)
                             + y0.z + wts[1] * (y1.z - y0.z)
                             + z0.z + wts[2] * (z1.z - z0.z);
                    float v3 = x0.w + wts[0] * (x1.w - x0.w)
                             + y0.w + wts[1] * (y1.w - y0.w)
                             + z0.w + wts[2] * (z1.w - z0.w);
                    sH[(ch + 0) * HSTRIDE + p_local] = fmaxf(v0, 0.f);
                    sH[(ch + 1) * HSTRIDE + p_local] = fmaxf(v1, 0.f);
                    sH[(ch + 2) * HSTRIDE + p_local] = fmaxf(v2, 0.f);
                    sH[(ch + 3) * HSTRIDE + p_local] = fmaxf(v3, 0.f);
                }
            }
        }
        __syncthreads();

        // ================= phase 2: tiled GEMM + layer2 =================
        // warp w -> points p0 = 8*w .. 8*w+7 ; lane -> j = 4*lane .. 4*lane+3
        {
            const int p0 = wid * 8;
            const int j0 = lane * 4;
            unsigned long long acc[4][4];   // [point-pair][j], f32x2 over (p even, p odd)
#pragma unroll
            for (int pp = 0; pp < 4; pp++)
#pragma unroll
                for (int j = 0; j < 4; j++) acc[pp][j] = 0ull;

#pragma unroll 4
            for (int kc = 0; kc < 32; kc++) {
                const int k = kc * 4;
                // W1T rows k..k+3, this lane's 4 j's (conflict-free lane-consecutive)
                float4 w0 = *(const float4*)&sW1T[(k + 0) * 128 + j0];
                float4 w1 = *(const float4*)&sW1T[(k + 1) * 128 + j0];
                float4 w2r = *(const float4*)&sW1T[(k + 2) * 128 + j0];
                float4 w3 = *(const float4*)&sW1T[(k + 3) * 128 + j0];
                // h rows k..k+3, 8 points -> natural f32x2 pairs (warp-broadcast)
                ulonglong2 h0p = *(const ulonglong2*)&sH[(k + 0) * HSTRIDE + p0];
                ulonglong2 h0q = *(const ulonglong2*)&sH[(k + 0) * HSTRIDE + p0 + 4];
                ulonglong2 h1p = *(const ulonglong2*)&sH[(k + 1) * HSTRIDE + p0];
                ulonglong2 h1q = *(const ulonglong2*)&sH[(k + 1) * HSTRIDE + p0 + 4];
                ulonglong2 h2p = *(const ulonglong2*)&sH[(k + 2) * HSTRIDE + p0];
                ulonglong2 h2q = *(const ulonglong2*)&sH[(k + 2) * HSTRIDE + p0 + 4];
                ulonglong2 h3p = *(const ulonglong2*)&sH[(k + 3) * HSTRIDE + p0];
                ulonglong2 h3q = *(const ulonglong2*)&sH[(k + 3) * HSTRIDE + p0 + 4];

#define K_STEP(WV, HP, HQ)                                                     \
                {                                                              \
                    unsigned long long d0 = dup2(WV.x);                        \
                    unsigned long long d1 = dup2(WV.y);                        \
                    unsigned long long d2 = dup2(WV.z);                        \
                    unsigned long long d3 = dup2(WV.w);                        \
                    acc[0][0] = fma2(HP.x, d0, acc[0][0]);                     \
                    acc[0][1] = fma2(HP.x, d1, acc[0][1]);                     \
                    acc[0][2] = fma2(HP.x, d2, acc[0][2]);                     \
                    acc[0][3] = fma2(HP.x, d3, acc[0][3]);                     \
                    acc[1][0] = fma2(HP.y, d0, acc[1][0]);                     \
                    acc[1][1] = fma2(HP.y, d1, acc[1][1]);                     \
                    acc[1][2] = fma2(HP.y, d2, acc[1][2]);                     \
                    acc[1][3] = fma2(HP.y, d3, acc[1][3]);                     \
                    acc[2][0] = fma2(HQ.x, d0, acc[2][0]);                     \
                    acc[2][1] = fma2(HQ.x, d1, acc[2][1]);                     \
                    acc[2][2] = fma2(HQ.x, d2, acc[2][2]);                     \
                    acc[2][3] = fma2(HQ.x, d3, acc[2][3]);                     \
                    acc[3][0] = fma2(HQ.y, d0, acc[3][0]);                     \
                    acc[3][1] = fma2(HQ.y, d1, acc[3][1]);                     \
                    acc[3][2] = fma2(HQ.y, d2, acc[3][2]);                     \
                    acc[3][3] = fma2(HQ.y, d3, acc[3][3]);                     \
                }
                K_STEP(w0, h0p, h0q)
                K_STEP(w1, h1p, h1q)
                K_STEP(w2r, h2p, h2q)
                K_STEP(w3, h3p, h3q)
#undef K_STEP
            }

            // epilogue: relu(acc + b1[j]) * w2[j], reduce over j (in-lane) then lanes
            float4 b1v = *(const float4*)&sb1[j0];
            float4 w2v = *(const float4*)&sw2[j0];
            float sums[8];
#pragma unroll
            for (int pp = 0; pp < 4; pp++) {
                float r0 = 0.f, r1 = 0.f, a0, a1;
                unpack2(acc[pp][0], a0, a1);
                r0 += fmaxf(a0 + b1v.x, 0.f) * w2v.x;
                r1 += fmaxf(a1 + b1v.x, 0.f) * w2v.x;
                unpack2(acc[pp][1], a0, a1);
                r0 += fmaxf(a0 + b1v.y, 0.f) * w2v.y;
                r1 += fmaxf(a1 + b1v.y, 0.f) * w2v.y;
                unpack2(acc[pp][2], a0, a1);
                r0 += fmaxf(a0 + b1v.z, 0.f) * w2v.z;
                r1 += fmaxf(a1 + b1v.z, 0.f) * w2v.z;
                unpack2(acc[pp][3], a0, a1);
                r0 += fmaxf(a0 + b1v.w, 0.f) * w2v.w;
                r1 += fmaxf(a1 + b1v.w, 0.f) * w2v.w;
                sums[2 * pp]     = r0;
                sums[2 * pp + 1] = r1;
            }
#pragma unroll
            for (int off = 16; off > 0; off >>= 1) {
#pragma unroll
                for (int i = 0; i < 8; i++)
                    sums[i] += __shfl_xor_sync(0xffffffffu, sums[i], off);
            }
            if (lane < 8) {
                int idx = base + p0 + lane;
                if (idx < n) out[idx] = sums[lane] + bias2;
            }
        }
        __syncthreads();
    }
}

// ---------------- launch ----------------
extern "C" void kernel_launch(void* const* d_in, const int* in_sizes, int n_in,
                              void* d_out, int out_size) {
    const float* expr = (const float*)d_in[0];
    const float* jqw  = (const float*)d_in[1];
    const float* xyz  = (const float*)d_in[2];
    const float* flx  = (const float*)d_in[3];
    const float* fly  = (const float*)d_in[4];
    const float* flz  = (const float*)d_in[5];
    const float* w0_v = (const float*)d_in[6];
    const float* w0_g = (const float*)d_in[7];
    const float* b0   = (const float*)d_in[8];
    const float* w1_v = (const float*)d_in[9];
    const float* w1_g = (const float*)d_in[10];
    const float* b1   = (const float*)d_in[11];
    const float* w2_v = (const float*)d_in[12];
    const float* w2_g = (const float*)d_in[13];
    const float* b2   = (const float*)d_in[14];
    float* out = (float*)d_out;

    int n = in_sizes[2] / 3;

    lines_kernel<<<dim3(64, 3), 32>>>(expr, jqw, flx, fly, flz);
    wnorm_kernel<<<129, 128>>>(w1_v, w1_g, w2_v, w2_g);
    table_kernel<<<dim3(64, 3), 128>>>(w0_v, w0_g, b0);

    cudaFuncSetAttribute(mlp_kernel,
                         cudaFuncAttributeMaxDynamicSharedMemorySize,
                         SM_FLOATS * sizeof(float));
    int nchunks = (n + CHUNK - 1) / CHUNK;
    int grid = 592;
    if (grid > nchunks) grid = nchunks;
    mlp_kernel<<<grid, TPB, SM_FLOATS * sizeof(float)>>>(xyz, b1, b2, out, n);
}

// round 10
// speedup vs baseline: 1.7408x; 1.0919x over previous
#include <cuda_runtime.h>
#include <cuda_bf16.h>
#include <math.h>

// ---------------- scratch (no allocation allowed) ----------------
__device__ float g_lines[3 * 2 * 64 * 32];   // [axis][bs/jaw][l][c]
__device__ float g_P[3 * 64 * 128];          // [axis][l][j] layer0-folded tables (+b0/3)
__device__ float g_W1T[128 * 128];           // weight-normed W1, TRANSPOSED [k][j]
__device__ float g_w2[128];                  // weight-normed w2 row

// ---------------- f32x2 packed helpers ----------------
__device__ __forceinline__ unsigned long long fma2(unsigned long long a,
                                                   unsigned long long b,
                                                   unsigned long long c) {
    unsigned long long d;
    asm("fma.rn.f32x2 %0, %1, %2, %3;" : "=l"(d) : "l"(a), "l"(b), "l"(c));
    return d;
}
__device__ __forceinline__ unsigned long long dup2(float s) {
    unsigned long long d;
    asm("mov.b64 %0, {%1, %1};" : "=l"(d) : "f"(s));
    return d;
}
__device__ __forceinline__ void unpack2(unsigned long long v, float& lo, float& hi) {
    asm("mov.b64 {%0, %1}, %2;" : "=f"(lo), "=f"(hi) : "l"(v));
}

// ---------------- kernel A: weighted line sums ----------------
__global__ void lines_kernel(const float* __restrict__ expr,
                             const float* __restrict__ jw,
                             const float* __restrict__ flx,
                             const float* __restrict__ fly,
                             const float* __restrict__ flz) {
    int l = blockIdx.x, a = blockIdx.y, c = threadIdx.x;
    const float* fl = (a == 0) ? flx : ((a == 1) ? fly : flz);
    const float* base = fl + l * 32 + c;
    float bs = 0.f, jaw = 0.f;
#pragma unroll 4
    for (int i = 0; i < 80; i++) bs += base[i * 2048] * expr[i];
#pragma unroll
    for (int i = 0; i < 16; i++) jaw += base[(80 + i) * 2048] * jw[i];
    g_lines[((a * 2 + 0) * 64 + l) * 32 + c] = bs;
    g_lines[((a * 2 + 1) * 64 + l) * 32 + c] = jaw;
}

// ---------------- kernel B: weight-norm W1 (transposed) and w2 ----------------
__global__ void wnorm_kernel(const float* __restrict__ w1_v,
                             const float* __restrict__ w1_g,
                             const float* __restrict__ w2_v,
                             const float* __restrict__ w2_g) {
    __shared__ float red[128];
    int j = blockIdx.x, t = threadIdx.x;
    const float* row = (j < 128) ? (w1_v + j * 128) : w2_v;
    float v = row[t];
    red[t] = v * v;
    __syncthreads();
    for (int s = 64; s > 0; s >>= 1) {
        if (t < s) red[t] += red[t + s];
        __syncthreads();
    }
    float g = (j < 128) ? w1_g[j] : w2_g[0];
    float scale = g / sqrtf(red[0]);
    if (j < 128) g_W1T[t * 128 + j] = v * scale;   // transposed: [k=t][j]
    else         g_w2[t] = v * scale;
}

// ---------------- kernel C: fold W0 (+ b0/3) into per-axis tables ----------------
__global__ void table_kernel(const float* __restrict__ w0_v,
                             const float* __restrict__ w0_g,
                             const float* __restrict__ b0) {
    int l = blockIdx.x, a = blockIdx.y, j = threadIdx.x;
    const float* vrow = w0_v + j * 192;
    float nn = 0.f;
#pragma unroll 8
    for (int c = 0; c < 192; c++) { float v = vrow[c]; nn += v * v; }
    float s = w0_g[j] / sqrtf(nn);
    const float* bs  = &g_lines[((a * 2 + 0) * 64 + l) * 32];
    const float* jl  = &g_lines[((a * 2 + 1) * 64 + l) * 32];
    float acc = 0.f;
#pragma unroll
    for (int c = 0; c < 32; c++) acc += vrow[32 * a + c] * bs[c];
#pragma unroll
    for (int c = 0; c < 32; c++) acc += vrow[96 + 32 * a + c] * jl[c];
    // fold b0/3 into each axis (lerp weights sum to 1 -> constants pass through)
    g_P[(a * 64 + l) * 128 + j] = s * acc + b0[j] * (1.0f / 3.0f);
}

// ---------------- kernel D: main per-point MLP ----------------
constexpr int TPB = 256;
constexpr int CHUNK = 128;             // points per chunk (16 per warp)
constexpr int HSTRIDE = 132;           // h0T row stride (floats), 16B-aligned pad

// smem (floats): tables 3*64*128 = 24576 (UNPADDED) | W1T 16384 | h0T 128*132 = 16896
constexpr int SM_T   = 0;
constexpr int SM_W1T = 24576;
constexpr int SM_H   = SM_W1T + 16384;            // 40960
constexpr int SM_FLOATS = SM_H + 128 * HSTRIDE;   // 57856 floats = 231424 bytes

__global__ __launch_bounds__(TPB, 1)
void mlp_kernel(const float* __restrict__ xyz,
                const float* __restrict__ b1,
                const float* __restrict__ b2p,
                float* __restrict__ out, int n) {
    extern __shared__ float sm[];
    float* sT   = sm + SM_T;
    float* sW1T = sm + SM_W1T;
    float* sH   = sm + SM_H;

    // ---- one-time shared fill (tables unpadded: direct float4 copy) ----
    {
        float4* dst = (float4*)sT;
        const float4* src = (const float4*)g_P;
        for (int i = threadIdx.x; i < 3 * 64 * 128 / 4; i += TPB) dst[i] = src[i];
    }
    {
        float4* dst = (float4*)sW1T;
        const float4* src = (const float4*)g_W1T;
        for (int i = threadIdx.x; i < 128 * 128 / 4; i += TPB) dst[i] = src[i];
    }
    __syncthreads();

    const float bias2 = __ldg(b2p);
    const int tid  = threadIdx.x;
    const int lane = tid & 31;
    const int wid  = tid >> 5;
    const int p_local = tid & 127;         // phase-1 point within chunk
    const int sub     = tid >> 7;          // phase-1 channel half (0..1)
    const int nchunks = (n + CHUNK - 1) / CHUNK;

    for (int c = blockIdx.x; c < nchunks; c += gridDim.x) {
        const int base = c * CHUNK;

        // ================= phase 1: h0 for 128 points -> sH[k][p] =================
        // thread -> point p_local, 64 channels (sub half). Rotated q schedule keeps
        // the unpadded-table bank quads spread (2-way max conflict).
        {
            const int idx = base + p_local;
            if (idx < n) {
                float coords[3];
                coords[0] = xyz[idx * 3 + 0];
                coords[1] = xyz[idx * 3 + 1];
                coords[2] = xyz[idx * 3 + 2];
                const float4* rowL[3];
                const float4* rowR[3];
                float wts[3];
#pragma unroll
                for (int a = 0; a < 3; a++) {
                    float p = fminf(fmaxf(coords[a], 0.f), 1.f) * 63.f;
                    float fl = floorf(p);
                    int l = (int)fl;
                    int r = min(l + 1, 63);
                    wts[a] = p - fl;
                    rowL[a] = (const float4*)&sT[(a * 64 + l) * 128];
                    rowR[a] = (const float4*)&sT[(a * 64 + r) * 128];
                }
#pragma unroll 4
                for (int c4 = 0; c4 < 16; c4++) {
                    const int q = (sub << 4) + ((c4 + lane) & 15);
                    const int ch = q << 2;
                    float4 x0 = rowL[0][q], x1 = rowR[0][q];
                    float4 y0 = rowL[1][q], y1 = rowR[1][q];
                    float4 z0 = rowL[2][q], z1 = rowR[2][q];
                    float v0 = x0.x + wts[0] * (x1.x - x0.x)
                             + y0.x + wts[1] * (y1.x - y0.x)
                             + z0.x + wts[2] * (z1.x - z0.x);
                    float v1 = x0.y + wts[0] * (x1.y - x0.y)
                             + y0.y + wts[1] * (y1.y - y0.y)
                             + z0.y + wts[2] * (z1.y - z0.y);
                    float v2 = x0.z + wts[0] * (x1.z - x0.z)
                             + y0.z + wts[1] * (y1.z - y0.z)
                             + z0.z + wts[2] * (z1.z - z0.z);
                    float v3 = x0.w + wts[0] * (x1.w - x0.w)
                             + y0.w + wts[1] * (y1.w - y0.w)
                             + z0.w + wts[2] * (z1.w - z0.w);
                    sH[(ch + 0) * HSTRIDE + p_local] = fmaxf(v0, 0.f);
                    sH[(ch + 1) * HSTRIDE + p_local] = fmaxf(v1, 0.f);
                    sH[(ch + 2) * HSTRIDE + p_local] = fmaxf(v2, 0.f);
                    sH[(ch + 3) * HSTRIDE + p_local] = fmaxf(v3, 0.f);
                }
            }
        }
        __syncthreads();

        // ================= phase 2: tiled GEMM + layer2 =================
        // warp w -> points p0 = 16*w .. 16*w+15 ; lane -> j = 4*lane .. 4*lane+3
        {
            const int p0 = wid * 16;
            const int j0 = lane * 4;
            unsigned long long acc[8][4];   // [point-pair][j], f32x2 over (p even, p odd)
#pragma unroll
            for (int pp = 0; pp < 8; pp++)
#pragma unroll
                for (int j = 0; j < 4; j++) acc[pp][j] = 0ull;

#pragma unroll 4
            for (int k = 0; k < 128; k++) {
                // W1T row k, this lane's 4 j's (conflict-free lane-consecutive)
                float4 wv = *(const float4*)&sW1T[k * 128 + j0];
                // h row k, 16 points -> 8 natural f32x2 pairs (warp-broadcast)
                const float* hrow = &sH[k * HSTRIDE + p0];
                ulonglong2 hA = *(const ulonglong2*)(hrow + 0);
                ulonglong2 hB = *(const ulonglong2*)(hrow + 4);
                ulonglong2 hC = *(const ulonglong2*)(hrow + 8);
                ulonglong2 hD = *(const ulonglong2*)(hrow + 12);
                unsigned long long d0 = dup2(wv.x);
                unsigned long long d1 = dup2(wv.y);
                unsigned long long d2 = dup2(wv.z);
                unsigned long long d3 = dup2(wv.w);
#define PP_STEP(I, HV)                                                         \
                acc[I][0] = fma2(HV, d0, acc[I][0]);                           \
                acc[I][1] = fma2(HV, d1, acc[I][1]);                           \
                acc[I][2] = fma2(HV, d2, acc[I][2]);                           \
                acc[I][3] = fma2(HV, d3, acc[I][3]);
                PP_STEP(0, hA.x) PP_STEP(1, hA.y)
                PP_STEP(2, hB.x) PP_STEP(3, hB.y)
                PP_STEP(4, hC.x) PP_STEP(5, hC.y)
                PP_STEP(6, hD.x) PP_STEP(7, hD.y)
#undef PP_STEP
            }

            // epilogue: relu(acc + b1[j]) * w2[j], reduce over j (in-lane) then lanes
            float4 b1v = __ldg((const float4*)(b1 + j0));
            float4 w2v = *(const float4*)&g_w2[j0];
            float sums[16];
#pragma unroll
            for (int pp = 0; pp < 8; pp++) {
                float r0 = 0.f, r1 = 0.f, a0, a1;
                unpack2(acc[pp][0], a0, a1);
                r0 += fmaxf(a0 + b1v.x, 0.f) * w2v.x;
                r1 += fmaxf(a1 + b1v.x, 0.f) * w2v.x;
                unpack2(acc[pp][1], a0, a1);
                r0 += fmaxf(a0 + b1v.y, 0.f) * w2v.y;
                r1 += fmaxf(a1 + b1v.y, 0.f) * w2v.y;
                unpack2(acc[pp][2], a0, a1);
                r0 += fmaxf(a0 + b1v.z, 0.f) * w2v.z;
                r1 += fmaxf(a1 + b1v.z, 0.f) * w2v.z;
                unpack2(acc[pp][3], a0, a1);
                r0 += fmaxf(a0 + b1v.w, 0.f) * w2v.w;
                r1 += fmaxf(a1 + b1v.w, 0.f) * w2v.w;
                sums[2 * pp]     = r0;
                sums[2 * pp + 1] = r1;
            }
#pragma unroll
            for (int off = 16; off > 0; off >>= 1) {
#pragma unroll
                for (int i = 0; i < 16; i++)
                    sums[i] += __shfl_xor_sync(0xffffffffu, sums[i], off);
            }
            if (lane < 16) {
                int idx = base + p0 + lane;
                if (idx < n) out[idx] = sums[lane] + bias2;
            }
        }
        __syncthreads();
    }
}

// ---------------- launch ----------------
extern "C" void kernel_launch(void* const* d_in, const int* in_sizes, int n_in,
                              void* d_out, int out_size) {
    const float* expr = (const float*)d_in[0];
    const float* jqw  = (const float*)d_in[1];
    const float* xyz  = (const float*)d_in[2];
    const float* flx  = (const float*)d_in[3];
    const float* fly  = (const float*)d_in[4];
    const float* flz  = (const float*)d_in[5];
    const float* w0_v = (const float*)d_in[6];
    const float* w0_g = (const float*)d_in[7];
    const float* b0   = (const float*)d_in[8];
    const float* w1_v = (const float*)d_in[9];
    const float* w1_g = (const float*)d_in[10];
    const float* b1   = (const float*)d_in[11];
    const float* w2_v = (const float*)d_in[12];
    const float* w2_g = (const float*)d_in[13];
    const float* b2   = (const float*)d_in[14];
    float* out = (float*)d_out;

    int n = in_sizes[2] / 3;

    lines_kernel<<<dim3(64, 3), 32>>>(expr, jqw, flx, fly, flz);
    wnorm_kernel<<<129, 128>>>(w1_v, w1_g, w2_v, w2_g);
    table_kernel<<<dim3(64, 3), 128>>>(w0_v, w0_g, b0);

    cudaFuncSetAttribute(mlp_kernel,
                         cudaFuncAttributeMaxDynamicSharedMemorySize,
                         SM_FLOATS * sizeof(float));
    int nchunks = (n + CHUNK - 1) / CHUNK;
    int grid = 148;                       // persistent: one smem fill per SM
    if (grid > nchunks) grid = nchunks;
    mlp_kernel<<<grid, TPB, SM_FLOATS * sizeof(float)>>>(xyz, b1, b2, out, n);
}